// round 1
// baseline (speedup 1.0000x reference)
#include <cuda_runtime.h>
#include <cstdint>
#include <cmath>

// FIRE bias: out[1,H,S,S], H=12, S=2048, W=32 hidden units.
// nd[i,j] = LR[|i-j|] * invLN[i]  (two 1-D precomputed arrays)
// bias[h](nd) is piecewise-linear in nd with <=32 ReLU breakpoints:
//   bias[h] = slope[region][h]*nd + icept[region][h]
// region = #{sorted thresholds <= nd}. Exact reassociation of the reference math.

#define SDIM 2048
#define HDIM 12
#define WDIM 32
#define NREG 33

__device__ float  g_LR[SDIM];
__device__ float  g_invLN[SDIM];
__device__ float  g_sortedT[WDIM];
__device__ float2 g_tab[NREG * HDIM];   // {slope, intercept}

__global__ void fire_pre(const float* __restrict__ w1,
                         const float* __restrict__ b1,
                         const float* __restrict__ w2,
                         const float* __restrict__ b2,
                         const float* __restrict__ cp,
                         const float* __restrict__ Lm,
                         const float* __restrict__ iL) {
    __shared__ float sW1[WDIM], sB1[WDIM], sT[WDIM];
    __shared__ int   sRank[WDIM];
    const int tid = threadIdx.x;
    const float c   = *cp;
    const float thr = fabsf((*Lm) * (*iL));

    // 1-D arrays: LR[d] = log((d+eps)*c + 1 + eps);  invLN[i] = 1/log(|c*(max(i,thr)+eps)| + 1 + eps)
    for (int d = tid; d < SDIM; d += blockDim.x) {
        g_LR[d] = logf(((float)d + 1e-6f) * c + 1.0f + 1e-6f);
        float pn = fmaxf((float)d, thr) + 1e-6f;
        g_invLN[d] = 1.0f / logf(fabsf(c * pn) + 1.0f + 1e-6f);
    }

    if (tid < WDIM) { sW1[tid] = w1[tid]; sB1[tid] = b1[tid]; }
    __syncthreads();
    if (tid < WDIM) {
        float w1v = sW1[tid];
        sT[tid] = (w1v != 0.0f) ? (-sB1[tid] / w1v) : 0.0f;
    }
    __syncthreads();
    if (tid < WDIM) {
        // rank-sort thresholds (index tiebreak)
        float t = sT[tid];
        int r = 0;
        for (int k = 0; k < WDIM; k++) {
            float tk = sT[k];
            if (tk < t || (tk == t && k < tid)) r++;
        }
        sRank[tid] = r;
        g_sortedT[r] = t;
    }
    __syncthreads();
    if (tid < NREG * HDIM) {
        const int r = tid / HDIM;
        const int h = tid % HDIM;
        float sl = 0.0f, ic = 0.0f;
        for (int w = 0; w < WDIM; w++) {
            const float w1v = sW1[w], b1v = sB1[w];
            bool act;
            if (w1v > 0.0f)      act = (sRank[w] < r);   // active when nd > t_w
            else if (w1v < 0.0f) act = (sRank[w] >= r);  // active when nd < t_w
            else                 act = (b1v > 0.0f);     // degenerate: constant unit
            if (act) {
                const float w2v = w2[h * WDIM + w];
                sl += w1v * w2v;
                ic += b1v * w2v;
            }
        }
        g_tab[tid] = make_float2(sl, ic + b2[h]);
    }
}

__global__ __launch_bounds__(512, 2)
void fire_main(float* __restrict__ out) {
    __shared__ float2 shTab[NREG * HDIM];
    __shared__ float  shT[WDIM];
    const int tid = threadIdx.x;
    for (int k = tid; k < NREG * HDIM; k += 512) shTab[k] = g_tab[k];
    if (tid < WDIM) shT[tid] = g_sortedT[tid];

    const int i = blockIdx.x;
    const float invln = g_invLN[i];
    __syncthreads();

    // thresholds in registers (broadcast LDS once)
    float t[WDIM];
#pragma unroll
    for (int k = 0; k < WDIM; k++) t[k] = shT[k];

    const int j0 = tid * 4;
    const float nd0 = g_LR[abs(i - j0)]       * invln;
    const float nd1 = g_LR[abs(i - (j0 + 1))] * invln;
    const float nd2 = g_LR[abs(i - (j0 + 2))] * invln;
    const float nd3 = g_LR[abs(i - (j0 + 3))] * invln;

    int r0 = 0, r1 = 0, r2 = 0, r3 = 0;
#pragma unroll
    for (int k = 0; k < WDIM; k++) {
        const float tk = t[k];
        r0 += (nd0 >= tk);
        r1 += (nd1 >= tk);
        r2 += (nd2 >= tk);
        r3 += (nd3 >= tk);
    }

    float* op = out + (size_t)i * SDIM + j0;
    if ((r0 == r1) & (r1 == r2) & (r2 == r3)) {
        // fast path: all 4 j's in the same linear region (dominant case)
        const float2* row = shTab + r0 * HDIM;
#pragma unroll
        for (int h = 0; h < HDIM; h++) {
            const float2 sb = row[h];
            float4 v = make_float4(fmaf(sb.x, nd0, sb.y), fmaf(sb.x, nd1, sb.y),
                                   fmaf(sb.x, nd2, sb.y), fmaf(sb.x, nd3, sb.y));
            *reinterpret_cast<float4*>(op + (size_t)h * SDIM * SDIM) = v;
        }
    } else {
#pragma unroll
        for (int h = 0; h < HDIM; h++) {
            const float2 a = shTab[r0 * HDIM + h];
            const float2 b = shTab[r1 * HDIM + h];
            const float2 cc = shTab[r2 * HDIM + h];
            const float2 d = shTab[r3 * HDIM + h];
            float4 v = make_float4(fmaf(a.x, nd0, a.y), fmaf(b.x, nd1, b.y),
                                   fmaf(cc.x, nd2, cc.y), fmaf(d.x, nd3, d.y));
            *reinterpret_cast<float4*>(op + (size_t)h * SDIM * SDIM) = v;
        }
    }
}

extern "C" void kernel_launch(void* const* d_in, const int* in_sizes, int n_in,
                              void* d_out, int out_size) {
    // inputs: x(unused), w1[32], b1[32], w2[12*32], b2[12], c, L_multiplier, init_L
    const float* w1 = (const float*)d_in[1];
    const float* b1 = (const float*)d_in[2];
    const float* w2 = (const float*)d_in[3];
    const float* b2 = (const float*)d_in[4];
    const float* c  = (const float*)d_in[5];
    const float* Lm = (const float*)d_in[6];
    const float* iL = (const float*)d_in[7];
    (void)in_sizes; (void)n_in; (void)out_size;

    fire_pre<<<1, 512>>>(w1, b1, w2, b2, c, Lm, iL);
    fire_main<<<SDIM, 512>>>((float*)d_out);
}

// round 5
// speedup vs baseline: 1.1280x; 1.1280x over previous
#include <cuda_runtime.h>
#include <cstdint>
#include <cmath>

// FIRE bias: out[1,H,S,S], H=12, S=2048, W=32.
// nd[i,j] = LR[|i-j|] * invLN[i]; bias[h] piecewise-linear in nd (<=32 ReLU knees).
// region found by binary search on LR[d] vs t_k*LN[i] (invLN folded out of compare,
// and into the per-block slope table). Continuity at knees makes tie rounding harmless.

#define SDIM 2048
#define HDIM 12
#define WDIM 32
#define NREG 33

__device__ float  g_LR[SDIM];
__device__ float  g_invLN[SDIM];
__device__ float  g_LN[SDIM];
__device__ float  g_sortedT[WDIM];
__device__ float2 g_tab[NREG * HDIM];   // {slope, intercept}

__global__ void fire_pre(const float* __restrict__ w1,
                         const float* __restrict__ b1,
                         const float* __restrict__ w2,
                         const float* __restrict__ b2,
                         const float* __restrict__ cp,
                         const float* __restrict__ Lm,
                         const float* __restrict__ iL) {
    __shared__ float sW1[WDIM], sB1[WDIM], sT[WDIM];
    __shared__ int   sRank[WDIM];
    const int tid = threadIdx.x;
    const float c   = *cp;
    const float thr = fabsf((*Lm) * (*iL));

    for (int d = tid; d < SDIM; d += blockDim.x) {
        g_LR[d] = logf(((float)d + 1e-6f) * c + 1.0f + 1e-6f);
        float pn = fmaxf((float)d, thr) + 1e-6f;
        float ln = logf(fabsf(c * pn) + 1.0f + 1e-6f);
        g_LN[d] = ln;
        g_invLN[d] = 1.0f / ln;
    }

    if (tid < WDIM) { sW1[tid] = w1[tid]; sB1[tid] = b1[tid]; }
    __syncthreads();
    if (tid < WDIM) {
        float w1v = sW1[tid];
        sT[tid] = (w1v != 0.0f) ? (-sB1[tid] / w1v) : 0.0f;
    }
    __syncthreads();
    if (tid < WDIM) {
        float t = sT[tid];
        int r = 0;
        for (int k = 0; k < WDIM; k++) {
            float tk = sT[k];
            if (tk < t || (tk == t && k < tid)) r++;
        }
        sRank[tid] = r;
        g_sortedT[r] = t;
    }
    __syncthreads();
    if (tid < NREG * HDIM) {
        const int r = tid / HDIM;
        const int h = tid % HDIM;
        float sl = 0.0f, ic = 0.0f;
        for (int w = 0; w < WDIM; w++) {
            const float w1v = sW1[w], b1v = sB1[w];
            bool act;
            if (w1v > 0.0f)      act = (sRank[w] < r);
            else if (w1v < 0.0f) act = (sRank[w] >= r);
            else                 act = (b1v > 0.0f);
            if (act) {
                const float w2v = w2[h * WDIM + w];
                sl += w1v * w2v;
                ic += b1v * w2v;
            }
        }
        g_tab[tid] = make_float2(sl, ic + b2[h]);
    }
#if __CUDA_ARCH__ >= 900
    cudaTriggerProgrammaticLaunchCompletion();
#endif
}

__global__ __launch_bounds__(512, 3)
void fire_main(float* __restrict__ out) {
#if __CUDA_ARCH__ >= 900
    cudaGridDependencySynchronize();
#endif
    __shared__ float2 shTab[NREG * HDIM];   // slope pre-multiplied by invLN[i]
    __shared__ float  sLRT[64];             // t_k * LN[i], padded with +inf
    const int tid = threadIdx.x;
    const int i   = blockIdx.x;

    const float invln = g_invLN[i];
    const float ln    = g_LN[i];
    for (int k = tid; k < NREG * HDIM; k += 512) {
        float2 v = g_tab[k];
        v.x *= invln;
        shTab[k] = v;
    }
    if (tid < 64)
        sLRT[tid] = (tid < WDIM) ? g_sortedT[tid] * ln : __int_as_float(0x7f800000);
    __syncthreads();

    const int j0 = tid * 4;
    const float lr0 = g_LR[abs(i - j0)];
    const float lr1 = g_LR[abs(i - (j0 + 1))];
    const float lr2 = g_LR[abs(i - (j0 + 2))];
    const float lr3 = g_LR[abs(i - (j0 + 3))];

    // branchless binary search: r = #{k : LR >= t_k*LN}  (region index, 0..32)
    int r0 = 0, r1 = 0, r2 = 0, r3 = 0;
#pragma unroll
    for (int s = 32; s >= 1; s >>= 1) {
        r0 += (lr0 >= sLRT[r0 + s - 1]) ? s : 0;
        r1 += (lr1 >= sLRT[r1 + s - 1]) ? s : 0;
        r2 += (lr2 >= sLRT[r2 + s - 1]) ? s : 0;
        r3 += (lr3 >= sLRT[r3 + s - 1]) ? s : 0;
    }

    float* op = out + (size_t)i * SDIM + j0;
    if ((r0 == r1) & (r1 == r2) & (r2 == r3)) {
        const float2* row = shTab + r0 * HDIM;
#pragma unroll
        for (int h = 0; h < HDIM; h++) {
            const float2 sb = row[h];
            float4 v = make_float4(fmaf(sb.x, lr0, sb.y), fmaf(sb.x, lr1, sb.y),
                                   fmaf(sb.x, lr2, sb.y), fmaf(sb.x, lr3, sb.y));
            __stcs(reinterpret_cast<float4*>(op + (size_t)h * SDIM * SDIM), v);
        }
    } else {
#pragma unroll
        for (int h = 0; h < HDIM; h++) {
            const float2 a = shTab[r0 * HDIM + h];
            const float2 b = shTab[r1 * HDIM + h];
            const float2 cc = shTab[r2 * HDIM + h];
            const float2 d = shTab[r3 * HDIM + h];
            float4 v = make_float4(fmaf(a.x, lr0, a.y), fmaf(b.x, lr1, b.y),
                                   fmaf(cc.x, lr2, cc.y), fmaf(d.x, lr3, d.y));
            __stcs(reinterpret_cast<float4*>(op + (size_t)h * SDIM * SDIM), v);
        }
    }
}

extern "C" void kernel_launch(void* const* d_in, const int* in_sizes, int n_in,
                              void* d_out, int out_size) {
    // inputs: x(unused), w1[32], b1[32], w2[12*32], b2[12], c, L_multiplier, init_L
    const float* w1 = (const float*)d_in[1];
    const float* b1 = (const float*)d_in[2];
    const float* w2 = (const float*)d_in[3];
    const float* b2 = (const float*)d_in[4];
    const float* c  = (const float*)d_in[5];
    const float* Lm = (const float*)d_in[6];
    const float* iL = (const float*)d_in[7];
    (void)in_sizes; (void)n_in; (void)out_size;

    fire_pre<<<1, 512>>>(w1, b1, w2, b2, c, Lm, iL);

    // fire_main launched with programmatic dependency on fire_pre: blocks begin
    // their prologue early and wait on cudaGridDependencySynchronize() before
    // touching the tables. Overlaps pre-kernel + launch latency.
    cudaLaunchConfig_t cfg = {};
    cfg.gridDim  = dim3(SDIM);
    cfg.blockDim = dim3(512);
    cfg.dynamicSmemBytes = 0;
    cfg.stream = 0;
    cudaLaunchAttribute attrs[1];
    attrs[0].id = cudaLaunchAttributeProgrammaticStreamSerialization;
    attrs[0].val.programmaticStreamSerializationAllowed = 1;
    cfg.attrs = attrs;
    cfg.numAttrs = 1;
    cudaLaunchKernelEx(&cfg, fire_main, (float*)d_out);
}